// round 3
// baseline (speedup 1.0000x reference)
#include <cuda_runtime.h>
#include <cstdint>

// Problem constants (shapes fixed by the dataset)
#define NMAX    50000
#define IN_DIM  256
#define W_DIM   128
// QK row layout: per node, 128 floats of q then 128 floats of k (256 floats = 1KB)
__device__ float d_QK[(size_t)NMAX * 256];

// ---------------------------------------------------------------------------
// Kernel 1: fused projection. C[M,128] = X[M,256] @ W^T + b, W = wq (blockIdx.y
// ==0) or wk (==1). Output interleaved into d_QK.
// 128x128 tile SGEMM, BK=8, 256 threads, 8x8 accumulators/thread.
// ---------------------------------------------------------------------------
__global__ __launch_bounds__(256) void sgemm_qk(
    const float* __restrict__ X,
    const float* __restrict__ Wq, const float* __restrict__ Bq,
    const float* __restrict__ Wk, const float* __restrict__ Bk,
    int M)
{
    __shared__ float As[8][128];   // As[k][m]
    __shared__ float Bs[8][128];   // Bs[k][n]

    const float* __restrict__ W  = blockIdx.y ? Wk : Wq;
    const float* __restrict__ Bv = blockIdx.y ? Bk : Bq;

    const int tid = threadIdx.x;
    const int tx  = tid & 15;        // n groups of 8
    const int ty  = tid >> 4;        // m groups of 8
    const int row0 = blockIdx.x * 128;

    const int l_row = tid >> 1;          // 0..127
    const int l_c4  = (tid & 1) * 4;     // 0 or 4

    float c[8][8];
    #pragma unroll
    for (int i = 0; i < 8; ++i)
        #pragma unroll
        for (int j = 0; j < 8; ++j) c[i][j] = 0.f;

    for (int kt = 0; kt < IN_DIM; kt += 8) {
        float4 av = make_float4(0.f, 0.f, 0.f, 0.f);
        const int gr = row0 + l_row;
        if (gr < M)
            av = *(const float4*)(X + (size_t)gr * IN_DIM + kt + l_c4);
        As[l_c4 + 0][l_row] = av.x;
        As[l_c4 + 1][l_row] = av.y;
        As[l_c4 + 2][l_row] = av.z;
        As[l_c4 + 3][l_row] = av.w;

        float4 bv = *(const float4*)(W + (size_t)l_row * IN_DIM + kt + l_c4);
        Bs[l_c4 + 0][l_row] = bv.x;
        Bs[l_c4 + 1][l_row] = bv.y;
        Bs[l_c4 + 2][l_row] = bv.z;
        Bs[l_c4 + 3][l_row] = bv.w;

        __syncthreads();

        #pragma unroll
        for (int k = 0; k < 8; ++k) {
            float4 a0 = *(const float4*)&As[k][ty * 8];
            float4 a1 = *(const float4*)&As[k][ty * 8 + 4];
            float4 b0 = *(const float4*)&Bs[k][tx * 8];
            float4 b1 = *(const float4*)&Bs[k][tx * 8 + 4];
            float a[8] = {a0.x, a0.y, a0.z, a0.w, a1.x, a1.y, a1.z, a1.w};
            float b[8] = {b0.x, b0.y, b0.z, b0.w, b1.x, b1.y, b1.z, b1.w};
            #pragma unroll
            for (int i = 0; i < 8; ++i)
                #pragma unroll
                for (int j = 0; j < 8; ++j)
                    c[i][j] += a[i] * b[j];
        }
        __syncthreads();
    }

    float bias[8];
    #pragma unroll
    for (int j = 0; j < 8; ++j) bias[j] = Bv[tx * 8 + j];

    #pragma unroll
    for (int i = 0; i < 8; ++i) {
        const int gr = row0 + ty * 8 + i;
        if (gr < M) {
            float* dst = d_QK + (size_t)gr * 256 + blockIdx.y * 128 + tx * 8;
            float4 v0 = make_float4(c[i][0] + bias[0], c[i][1] + bias[1],
                                    c[i][2] + bias[2], c[i][3] + bias[3]);
            float4 v1 = make_float4(c[i][4] + bias[4], c[i][5] + bias[5],
                                    c[i][6] + bias[6], c[i][7] + bias[7]);
            *(float4*)(dst + 0) = v0;
            *(float4*)(dst + 4) = v1;
        }
    }
}

// ---------------------------------------------------------------------------
// Kernel 2: per-edge gather + dot. 8 lanes per edge; contiguous 128B float4
// slabs of q row (src) and k row (dst); shfl reduce; leader writes /sqrt(128).
// edge_index is int32 (JAX downcasts int64 silently with x64 disabled).
// Indices defensively clamped so a bad index theory shows as rel_err, not a crash.
// ---------------------------------------------------------------------------
__global__ __launch_bounds__(256) void edge_attn(
    const int* __restrict__ ei,  // [2, E] int32
    float* __restrict__ out, int E, int M)
{
    const int e   = (blockIdx.x * blockDim.x + threadIdx.x) >> 3;
    const int sub = threadIdx.x & 7;
    if (e >= E) return;

    int s = ei[e];
    int d = ei[E + e];
    s = min(max(s, 0), M - 1);
    d = min(max(d, 0), M - 1);

    const float4* __restrict__ qp = (const float4*)(d_QK + (size_t)s * 256);
    const float4* __restrict__ kp = (const float4*)(d_QK + (size_t)d * 256 + 128);

    float acc = 0.f;
    #pragma unroll
    for (int it = 0; it < 4; ++it) {
        float4 q = qp[it * 8 + sub];
        float4 k = kp[it * 8 + sub];
        acc += q.x * k.x + q.y * k.y + q.z * k.z + q.w * k.w;
    }
    acc += __shfl_xor_sync(0xffffffffu, acc, 1);
    acc += __shfl_xor_sync(0xffffffffu, acc, 2);
    acc += __shfl_xor_sync(0xffffffffu, acc, 4);

    if (sub == 0)
        out[e] = acc * 0.08838834764831845f;   // 1/sqrt(128)
}

// ---------------------------------------------------------------------------
extern "C" void kernel_launch(void* const* d_in, const int* in_sizes, int n_in,
                              void* d_out, int out_size)
{
    // Resolve inputs by element count (robust to metadata ordering):
    //   inputs     : M*256   (~12.8M)
    //   weights    : 128*256 = 32768 (two of them; first = wq_w, second = wk_w)
    //   biases     : 128             (two; first = wq_b, second = wk_b)
    //   edge_index : 2*E     (~3.2M)
    const float *X = nullptr, *Wq = nullptr, *Bq = nullptr, *Wk = nullptr, *Bk = nullptr;
    const int   *ei = nullptr;
    int ei_elems = 0, x_elems = 0;

    for (int i = 0; i < n_in; ++i) {
        const int sz = in_sizes[i];
        if (sz == W_DIM * IN_DIM) {            // 32768: a weight
            if (!Wq) Wq = (const float*)d_in[i];
            else     Wk = (const float*)d_in[i];
        } else if (sz == W_DIM) {              // 128: a bias
            if (!Bq) Bq = (const float*)d_in[i];
            else     Bk = (const float*)d_in[i];
        } else if (sz > 4000000) {             // 12.8M: node features
            X = (const float*)d_in[i];
            x_elems = sz;
        } else {                               // 3.2M: edge index
            ei = (const int*)d_in[i];
            ei_elems = sz;
        }
    }

    const int M = x_elems / IN_DIM;    // 50000
    const int E = ei_elems / 2;        // 1600000
    float* out = (float*)d_out;

    dim3 grid_g((M + 127) / 128, 2);
    sgemm_qk<<<grid_g, 256>>>(X, Wq, Bq, Wk, Bk, M);

    const int threads = 256;
    const int blocks  = (E * 8 + threads - 1) / threads;
    edge_attn<<<blocks, threads>>>(ei, out, E, M);
}